// round 15
// baseline (speedup 1.0000x reference)
#include <cuda_runtime.h>
#include <cstdint>

#define Bc 32
#define Lc 4096
#define Hc 256
#define Nc 512
#define NROWS (Bc * Nc)          // 16384
#define TT 136
#define PROWS (Bc * TT)          // 4352
#define SLOPE 0.2f
#define NEGINF (-3.4028234663852886e38f)
#define EDGECAP (Nc * (Nc - 1) * 2)
#define WCAP 256

// copy partition: 2048 chunks x 4096 float4 (16KB each), 256 chunks per batch.
// E (scatter) takes the LAST 10 chunks of each batch (never contain centers,
// which live in the first 8 chunks of a batch). Others split the remaining
// 1728 chunks linearly over the complement set.
#define CPY_A 512   // mega0 (tail)
#define CPY_B 576   // nodeStats (head)
#define CPY_C 512   // edge (head)
#define CPY_D 128   // gemm1 (head)
#define CPY_E 320   // scatter (head)  = 32 batches x 10 chunks

typedef unsigned long long u64;
typedef unsigned int u32;

// ---------------- scratch ----------------
__device__ __align__(16) float g_Y[(size_t)PROWS * 512];
__device__ __align__(16) float g_node[(size_t)NROWS * 256];
__device__ __align__(16) float g_agg[(size_t)NROWS * 256];
__device__ __align__(16) float g_add[(size_t)NROWS * 256];
__device__ float g_AT[NROWS];
__device__ float g_AS[NROWS];
__device__ float g_AE[2];
__device__ float g_E[2][256];
__device__ float g_w0[NROWS];
__device__ float g_w1[NROWS];
__device__ int   g_hn[NROWS];
__device__ int   g_bhas[Bc];
__device__ int   g_rowcnt[NROWS];
__device__ int   g_rowoff[NROWS];
__device__ int   g_cand[(size_t)Bc * EDGECAP];
__device__ int   g_rows[NROWS];
__device__ int   g_nact;
__device__ int   g_clist[(size_t)Bc * 128 * 512];
__device__ int   g_ccnt[Bc * 128];

// ---------------- helpers ----------------
__device__ __forceinline__ u32 f2tf32(float f) {
    u32 r;
    asm("cvt.rna.tf32.f32 %0, %1;" : "=r"(r) : "f"(f));
    return r;
}
__device__ __forceinline__ void tf32split(float a, u32& hi, u32& lo) {
    hi = f2tf32(a);
    lo = f2tf32(a - __uint_as_float(hi));
}

#define MMA_TF32(C0, C1, C2, C3, A0, A1, A2, A3, B0, B1)                        \
    asm volatile(                                                                \
        "mma.sync.aligned.m16n8k8.row.col.f32.tf32.tf32.f32 "                    \
        "{%0,%1,%2,%3}, {%4,%5,%6,%7}, {%8,%9}, {%0,%1,%2,%3};"                  \
        : "+f"(C0), "+f"(C1), "+f"(C2), "+f"(C3)                                 \
        : "r"(A0), "r"(A1), "r"(A2), "r"(A3), "r"(B0), "r"(B1))

// ---------------- copy helpers ----------------
// Chunk id c in [0,2048). Batch = c>>8 (256 chunks per batch), pos = c&255.
// E-set = pos in [246,256). Linear index mapping for the complement (pos<246):
//   lin = batch*246 + pos, lin in [0, 7872)... wait total non-E = 2048-320 = 1728.
// (32 batches x 246 chunks = 7872? No: 256-10=246 -> 32*246=7872. That's wrong.)
// Correction: 2048 chunks total over 32 batches => 64 chunks per batch.
// 8,388,608 float4 / 4096 = 2048 chunks; per batch = 2048/32 = 64 chunks.
// Centers live in first 32768 floats = 8192 float4 = 2 chunks of each batch.
// E takes the last 10 chunks of each batch: pos in [54,64).
__device__ __forceinline__ void copyChunk(float4* __restrict__ dst,
                                          const float4* __restrict__ src,
                                          int cblk, int tid)
{
    size_t base = ((size_t)cblk << 12) + tid;
#pragma unroll
    for (int i = 0; i < 16; i++) dst[base + (i << 8)] = src[base + (i << 8)];
}
// non-E linear index -> chunk id (pos in [0,54), 54 per batch, 32*54 = 1728)
__device__ __forceinline__ int mapNonE(int lin) {
    int b = lin / 54;
    int p = lin - b * 54;
    return (b << 6) + p;
}
// E linear index -> chunk id (pos in [54,64), 10 per batch, 32*10 = 320)
__device__ __forceinline__ int mapE(int lin) {
    int b = lin / 10;
    int p = lin - b * 10;
    return (b << 6) + 54 + p;
}

#define AS_STRIDE 20
#define BS_STRIDE 136

// ============================================================================
// L1: gemm0 tf32-split (blocks 0..271) + build (272..303) + copyA (tail)
// ============================================================================
__global__ __launch_bounds__(256) void mega0Kernel(
    float* __restrict__ out, const float* __restrict__ emb,
    const float* __restrict__ W_trip,
    const int* __restrict__ asp_st, const int* __restrict__ asp_len,
    const int* __restrict__ opi_st, const int* __restrict__ opi_len,
    const float* __restrict__ edge_emb, const float* __restrict__ W_attn,
    const float* __restrict__ W_gat)
{
    cudaTriggerProgrammaticLaunchCompletion();
    int blk = blockIdx.x, tid = threadIdx.x;

    if (blk >= 304) {
        copyChunk((float4*)out, (const float4*)emb, mapNonE(blk - 304), tid);
        return;
    }

    if (blk < 272) {
        __shared__ __align__(16) u32 AsH[64 * AS_STRIDE];
        __shared__ __align__(16) u32 AsL[64 * AS_STRIDE];
        __shared__ __align__(16) u32 BsH[16 * BS_STRIDE];
        __shared__ __align__(16) u32 BsL[16 * BS_STRIDE];

        int bc = blk & 3, br = blk >> 2;
        int lane = tid & 31, wid = tid >> 5;
        int wm = wid & 3, wn = wid >> 2;

        int aRow = tid >> 2;
        int r = br * 64 + aRow;
        int b = r / TT, t = r - b * TT;
        const float* Ap = emb + ((size_t)(b * Lc + t)) * 256 + (tid & 3) * 4;
        int asw = aRow * AS_STRIDE + (tid & 3) * 4;

        int bkr = tid >> 4, bcg = (tid & 15) * 8;
        int j0 = bc * 128 + bcg;
        int half = (j0 >= 256);
        const float* Bp = W_trip + (size_t)(half * 256 + bkr) * 256 + (j0 - half * 256);
        int bsw = bkr * BS_STRIDE + bcg;

        float C[8][4];
#pragma unroll
        for (int j = 0; j < 8; j++)
#pragma unroll
            for (int i = 0; i < 4; i++) C[j][i] = 0.f;

        int g = lane >> 2, cc = lane & 3;

        float4 av = *(const float4*)Ap;
        float4 bv[2];
        bv[0] = *(const float4*)Bp;
        bv[1] = *(const float4*)(Bp + 4);

        for (int kc = 0; kc < 16; kc++) {
            {
                u32 h, l;
                tf32split(av.x, h, l); AsH[asw + 0] = h; AsL[asw + 0] = l;
                tf32split(av.y, h, l); AsH[asw + 1] = h; AsL[asw + 1] = l;
                tf32split(av.z, h, l); AsH[asw + 2] = h; AsL[asw + 2] = l;
                tf32split(av.w, h, l); AsH[asw + 3] = h; AsL[asw + 3] = l;
#pragma unroll
                for (int q = 0; q < 2; q++) {
                    tf32split(bv[q].x, h, l); BsH[bsw + q * 4 + 0] = h; BsL[bsw + q * 4 + 0] = l;
                    tf32split(bv[q].y, h, l); BsH[bsw + q * 4 + 1] = h; BsL[bsw + q * 4 + 1] = l;
                    tf32split(bv[q].z, h, l); BsH[bsw + q * 4 + 2] = h; BsL[bsw + q * 4 + 2] = l;
                    tf32split(bv[q].w, h, l); BsH[bsw + q * 4 + 3] = h; BsL[bsw + q * 4 + 3] = l;
                }
            }
            __syncthreads();
            bool more = (kc < 15);
            if (more) {
                av = *(const float4*)(Ap + (kc + 1) * 16);
                const float* bp = Bp + (size_t)((kc + 1) * 16) * 256;
                bv[0] = *(const float4*)bp;
                bv[1] = *(const float4*)(bp + 4);
            }
#pragma unroll
            for (int ks = 0; ks < 16; ks += 8) {
                int ra = (wm * 16 + g) * AS_STRIDE + ks + cc;
                int rb = (wm * 16 + g + 8) * AS_STRIDE + ks + cc;
                u32 ah0 = AsH[ra],     ah1 = AsH[rb];
                u32 ah2 = AsH[ra + 4], ah3 = AsH[rb + 4];
                u32 al0 = AsL[ra],     al1 = AsL[rb];
                u32 al2 = AsL[ra + 4], al3 = AsL[rb + 4];
                const u32* bh0p = &BsH[(ks + cc)     * BS_STRIDE + wn * 64 + g];
                const u32* bh1p = &BsH[(ks + cc + 4) * BS_STRIDE + wn * 64 + g];
                const u32* bl0p = &BsL[(ks + cc)     * BS_STRIDE + wn * 64 + g];
                const u32* bl1p = &BsL[(ks + cc + 4) * BS_STRIDE + wn * 64 + g];
#pragma unroll
                for (int j = 0; j < 8; j++) {
                    u32 bh0 = bh0p[j * 8], bh1 = bh1p[j * 8];
                    u32 bl0 = bl0p[j * 8], bl1 = bl1p[j * 8];
                    MMA_TF32(C[j][0], C[j][1], C[j][2], C[j][3],
                             ah0, ah1, ah2, ah3, bh0, bh1);
                    MMA_TF32(C[j][0], C[j][1], C[j][2], C[j][3],
                             ah0, ah1, ah2, ah3, bl0, bl1);
                    MMA_TF32(C[j][0], C[j][1], C[j][2], C[j][3],
                             al0, al1, al2, al3, bh0, bh1);
                }
            }
            __syncthreads();
        }

        int rr0 = br * 64 + wm * 16 + g;
        int rr1 = rr0 + 8;
#pragma unroll
        for (int j = 0; j < 8; j++) {
            int col = bc * 128 + wn * 64 + j * 8 + 2 * cc;
            float2 v0 = make_float2(C[j][0], C[j][1]);
            float2 v1 = make_float2(C[j][2], C[j][3]);
            *(float2*)&g_Y[(size_t)rr0 * 512 + col] = v0;
            *(float2*)&g_Y[(size_t)rr1 * 512 + col] = v1;
        }
        return;
    }

    // ---- build ----
    {
        int bb = blk - 272;
        int base = bb * Nc;
        __shared__ int ka[512], ko[512], cen[512];
        __shared__ int wsum[8];
        __shared__ int sc_cnt[128];
        for (int i = tid; i < 512; i += 256) {
            int st = asp_st[base + i], ln = asp_len[base + i];
            int so = opi_st[base + i], lo = opi_len[base + i];
            ka[i] = st | (ln << 16);
            ko[i] = so | (lo << 16);
            cen[i] = (st + so) >> 1;
        }
        if (tid < 128) sc_cnt[tid] = 0;
        __syncthreads();

        int t0 = 2 * tid, t1 = t0 + 1;
        int ka0 = ka[t0], ko0 = ko[t0], ce0 = cen[t0];
        int ka1 = ka[t1], ko1 = ko[t1], ce1 = cen[t1];
        int c0 = 0, c1 = 0, r0 = 0, r1 = 0;
        for (int s = 0; s < 512; s++) {
            int kas = ka[s], kos = ko[s], ces = cen[s];
            if (s != t0) c0 += (kas == ka0) + (kos == ko0);
            if (s != t1) c1 += (kas == ka1) + (kos == ko1);
            r0 += (s < t0 && ces == ce0);
            r1 += (s < t1 && ces == ce1);
        }
        int ps = c0 + c1;
        int lane = tid & 31, w = tid >> 5;
        int v = ps;
#pragma unroll
        for (int o = 1; o < 32; o <<= 1) {
            int n = __shfl_up_sync(0xffffffffu, v, o);
            if (lane >= o) v += n;
        }
        if (lane == 31) wsum[w] = v;
        __syncthreads();
        if (tid == 0) {
            int run = 0;
#pragma unroll
            for (int i = 0; i < 8; i++) { int x = wsum[i]; wsum[i] = run; run += x; }
        }
        __syncthreads();
        int off = v - ps + wsum[w];
        g_rowcnt[base + t0] = c0;
        g_rowcnt[base + t1] = c1;
        int p0 = bb * EDGECAP + off;
        int p1 = p0 + c0;
        g_rowoff[base + t0] = p0;
        g_rowoff[base + t1] = p1;
        for (int s = 0; s < 512; s++) {
            int kas = ka[s], kos = ko[s];
            if (s != t0) {
                if (kas == ka0) g_cand[p0++] = s;
                if (kos == ko0) g_cand[p0++] = s | (1 << 16);
            }
            if (s != t1) {
                if (kas == ka1) g_cand[p1++] = s;
                if (kos == ko1) g_cand[p1++] = s | (1 << 16);
            }
        }
        g_clist[((size_t)(bb * 128 + ce0) << 9) + r0] = t0;
        g_clist[((size_t)(bb * 128 + ce1) << 9) + r1] = t1;
        atomicAdd(&sc_cnt[ce0], 1);
        atomicAdd(&sc_cnt[ce1], 1);
        __syncthreads();
        if (tid < 128) g_ccnt[bb * 128 + tid] = sc_cnt[tid];

        if (bb == 0) {
            int h = tid;
#pragma unroll
            for (int e = 0; e < 2; e++) {
                float s = 0.f;
                for (int k = 0; k < 256; k++)
                    s += edge_emb[e * 256 + k] * W_gat[(size_t)(256 + k) * 256 + h];
                g_E[e][h] = s;
            }
            if (tid < 2) {
                float sa = 0.f;
                for (int k = 0; k < 256; k++) {
                    float vv = edge_emb[tid * 256 + k];
                    vv = (vv >= 0.f) ? vv : SLOPE * vv;
                    sa += vv * W_attn[512 + k];
                }
                g_AE[tid] = sa;
            }
            if (tid >= 4 && tid < 4 + Bc) g_bhas[tid - 4] = 0;
            if (tid == 2) g_nact = 0;
        }
    }
}

// ============================================================================
// L2: copyB (0..575, FIRST) + nodeStats (576..4671)   [PDL secondary]
// ============================================================================
__global__ __launch_bounds__(256) void nodeStatsKernel(
    float* __restrict__ out, const float* __restrict__ emb,
    const int* __restrict__ asp_st, const int* __restrict__ asp_len,
    const int* __restrict__ opi_st, const int* __restrict__ opi_len,
    const int* __restrict__ sent, const float* __restrict__ W_trip,
    const float* __restrict__ b_trip, const float* __restrict__ W_attn)
{
    cudaTriggerProgrammaticLaunchCompletion();
    int blk = blockIdx.x, tid = threadIdx.x;
    if (blk < CPY_B) {
        copyChunk((float4*)out, (const float4*)emb, mapNonE(CPY_A + blk), tid);
        return;
    }
    cudaGridDependencySynchronize();

    int cblk = blk - CPY_B;
    int rib = tid >> 6;
    int c4 = tid & 63;
    int row = cblk * 4 + rib;
    int b = row >> 9;
    const float4* Yb = (const float4*)(g_Y + (size_t)b * TT * 512);

    int ast = asp_st[row], aln = asp_len[row];
    int ost = opi_st[row], oln = opi_len[row];

    float4 asum = make_float4(0.f, 0.f, 0.f, 0.f);
#pragma unroll 4
    for (int k = 0; k <= aln; k++) {
        float4 v = Yb[(size_t)(ast + k) * 128 + c4];
        asum.x += v.x; asum.y += v.y; asum.z += v.z; asum.w += v.w;
    }
    float4 osum = make_float4(0.f, 0.f, 0.f, 0.f);
#pragma unroll 4
    for (int k = 0; k <= oln; k++) {
        float4 v = Yb[(size_t)(ost + k) * 128 + 64 + c4];
        osum.x += v.x; osum.y += v.y; osum.z += v.z; osum.w += v.w;
    }
    float ia = 1.f / (float)(aln + 1), io = 1.f / (float)(oln + 1);
    int sid = sent[row];
    float4 wt = ((const float4*)W_trip)[(size_t)(512 + sid) * 64 + c4];
    float4 bt = ((const float4*)b_trip)[c4];
    float4 v4;
    v4.x = asum.x * ia + osum.x * io + wt.x + bt.x;
    v4.y = asum.y * ia + osum.y * io + wt.y + bt.y;
    v4.z = asum.z * ia + osum.z * io + wt.z + bt.z;
    v4.w = asum.w * ia + osum.w * io + wt.w + bt.w;
    ((float4*)g_node)[((size_t)row << 6) + c4] = v4;

    float4 lv;
    lv.x = (v4.x >= 0.f) ? v4.x : SLOPE * v4.x;
    lv.y = (v4.y >= 0.f) ? v4.y : SLOPE * v4.y;
    lv.z = (v4.z >= 0.f) ? v4.z : SLOPE * v4.z;
    lv.w = (v4.w >= 0.f) ? v4.w : SLOPE * v4.w;
    float4 wat = ((const float4*)W_attn)[c4];
    float4 was = ((const float4*)W_attn)[64 + c4];
    float at = lv.x * wat.x + lv.y * wat.y + lv.z * wat.z + lv.w * wat.w;
    float as = lv.x * was.x + lv.y * was.y + lv.z * was.z + lv.w * was.w;
#pragma unroll
    for (int o = 16; o; o >>= 1) {
        at += __shfl_xor_sync(0xffffffffu, at, o);
        as += __shfl_xor_sync(0xffffffffu, as, o);
    }
    __shared__ float sAt[8], sAs[8];
    int w = tid >> 5;
    if ((tid & 31) == 0) { sAt[w] = at; sAs[w] = as; }
    __syncthreads();
    if (c4 == 0) {
        int w0 = rib * 2;
        g_AT[row] = sAt[w0] + sAt[w0 + 1];
        g_AS[row] = sAs[w0] + sAs[w0 + 1];
    }
}

// ============================================================================
// L3: copyC (0..511, FIRST) + edge (512..2559)   [PDL secondary]
// ============================================================================
__global__ __launch_bounds__(256) void edgeKernel(
    float* __restrict__ out, const float* __restrict__ emb,
    const float* __restrict__ b_attn)
{
    cudaTriggerProgrammaticLaunchCompletion();
    int blk = blockIdx.x, tid = threadIdx.x;
    if (blk < CPY_C) {
        copyChunk((float4*)out, (const float4*)emb, mapNonE(CPY_A + CPY_B + blk), tid);
        return;
    }
    cudaGridDependencySynchronize();

    int cblk = blk - CPY_C;
    __shared__ int   s_cand[8][WCAP];
    __shared__ float s_sc[8][WCAP];
    int warp = tid >> 5, lane = tid & 31;
    int row = cblk * 8 + warp;
    int b = row >> 9, bs = b * Nc;

    int m1 = g_rowcnt[row];
    if (m1 == 0) {
        if (lane == 0) g_hn[row] = 0;
        return;
    }
    if (m1 > WCAP) m1 = WCAP;
    int off = g_rowoff[row];
    for (int e = lane; e < m1; e += 32) s_cand[warp][e] = g_cand[off + e];

    const float* rp = g_node + ((size_t)row << 8);
    float nT[8];
#pragma unroll
    for (int k = 0; k < 8; k++) nT[k] = rp[lane + 32 * k];
    __syncwarp();

    float atv = g_AT[row], bat = b_attn[0];
    int m2 = 0;
    for (int e = 0; e < m1; e++) {
        int cd = s_cand[warp][e];
        int s = cd & 0xffff;
        const float* ns = g_node + ((size_t)(bs + s) << 8);
        float d = 0.f;
#pragma unroll
        for (int k = 0; k < 8; k++) d += nT[k] * ns[lane + 32 * k];
#pragma unroll
        for (int o = 16; o; o >>= 1) d += __shfl_xor_sync(0xffffffffu, d, o);
        if (lane == 0) {
            if (d > 0.f) { s_sc[warp][e] = atv + g_AS[bs + s] + g_AE[cd >> 16] + bat; m2++; }
            else s_sc[warp][e] = NEGINF;
        }
    }
    m2 = __shfl_sync(0xffffffffu, m2, 0);
    float invden = 0.f;
    if (lane == 0) {
        g_hn[row] = (m2 > 0) ? 1 : 0;
        if (m2 > 0) {
            atomicOr(&g_bhas[b], 1);
            int p = atomicAdd(&g_nact, 1);
            g_rows[p] = row;
            float mx = NEGINF;
            for (int e = 0; e < m1; e++) mx = fmaxf(mx, s_sc[warp][e]);
            float den = 0.f, w0 = 0.f, w1 = 0.f;
            for (int e = 0; e < m1; e++) {
                float we = expf(s_sc[warp][e] - mx);
                s_sc[warp][e] = we;
                den += we;
                if ((s_cand[warp][e] >> 16) == 0) w0 += we; else w1 += we;
            }
            invden = 1.f / den;
            g_w0[row] = w0 / den;
            g_w1[row] = w1 / den;
        }
    }
    invden = __shfl_sync(0xffffffffu, invden, 0);
    __syncwarp();
    if (m2 > 0) {
        float acc[8];
#pragma unroll
        for (int k = 0; k < 8; k++) acc[k] = 0.f;
        for (int e = 0; e < m1; e++) {
            float we = s_sc[warp][e];
            if (we != 0.f) {
                int s = s_cand[warp][e] & 0xffff;
                const float* ns = g_node + ((size_t)(bs + s) << 8);
#pragma unroll
                for (int k = 0; k < 8; k++) acc[k] += we * ns[lane + 32 * k];
            }
        }
        float* ag = g_agg + ((size_t)row << 8);
#pragma unroll
        for (int k = 0; k < 8; k++) ag[lane + 32 * k] = acc[k] * invden;
    }
}

// ============================================================================
// L4: copyD (0..127, FIRST) + GEMM1 tf32 (128..639)   [PDL secondary]
// ============================================================================
__global__ __launch_bounds__(256) void gemm1Kernel(
    float* __restrict__ out, const float* __restrict__ emb,
    const float* __restrict__ W, const float* __restrict__ bias)
{
    cudaTriggerProgrammaticLaunchCompletion();
    int blk = blockIdx.x, tid = threadIdx.x;
    if (blk < CPY_D) {
        copyChunk((float4*)out, (const float4*)emb,
                  mapNonE(CPY_A + CPY_B + CPY_C + blk), tid);
        return;
    }
    cudaGridDependencySynchronize();

    int tblk = blk - CPY_D;
    int nact = g_nact;
    int bc = tblk & 1, br = tblk >> 1;
    if (br * 64 >= nact) return;
    int nrows = nact - br * 64;
    if (nrows > 64) nrows = 64;

    __shared__ __align__(16) u32 As[2][64 * AS_STRIDE];
    __shared__ __align__(16) u32 Bs[2][16 * BS_STRIDE];
    __shared__ float sB[128], sE0[128], sE1[128];
    __shared__ int rows[64];

    int lane = tid & 31, wid = tid >> 5;
    int wm = wid & 3, wn = wid >> 2;

    if (tid < 64) rows[tid] = g_rows[br * 64 + (tid < nrows ? tid : nrows - 1)];
    if (tid < 128) {
        int c = bc * 128 + tid;
        sB[tid]  = bias[c];
        sE0[tid] = g_E[0][c];
        sE1[tid] = g_E[1][c];
    }
    __syncthreads();

    const float* Ap = g_agg + ((size_t)rows[tid >> 2] << 8) + (tid & 3) * 4;
    int asw = (tid >> 2) * AS_STRIDE + (tid & 3) * 4;
    int bkr = tid >> 4, bcg = (tid & 15) * 8;
    const float* Bp = W + (size_t)bkr * 256 + bc * 128 + bcg;
    int bsw = bkr * BS_STRIDE + bcg;

    float C[8][4];
#pragma unroll
    for (int j = 0; j < 8; j++)
#pragma unroll
        for (int i = 0; i < 4; i++) C[j][i] = 0.f;

    int g = lane >> 2, cc = lane & 3;

    {
        float4 av = *(const float4*)Ap;
        As[0][asw + 0] = f2tf32(av.x); As[0][asw + 1] = f2tf32(av.y);
        As[0][asw + 2] = f2tf32(av.z); As[0][asw + 3] = f2tf32(av.w);
#pragma unroll
        for (int l = 0; l < 2; l++) {
            float4 bv = *(const float4*)(Bp + l * 4);
            Bs[0][bsw + l * 4 + 0] = f2tf32(bv.x); Bs[0][bsw + l * 4 + 1] = f2tf32(bv.y);
            Bs[0][bsw + l * 4 + 2] = f2tf32(bv.z); Bs[0][bsw + l * 4 + 3] = f2tf32(bv.w);
        }
    }
    __syncthreads();

    for (int kc = 0; kc < 16; kc++) {
        int cur = kc & 1;
        float4 av; float4 bv[2];
        bool more = (kc < 15);
        if (more) {
            av = *(const float4*)(Ap + (kc + 1) * 16);
            const float* bp = Bp + (size_t)((kc + 1) * 16) * 256;
#pragma unroll
            for (int l = 0; l < 2; l++) bv[l] = *(const float4*)(bp + l * 4);
        }
#pragma unroll
        for (int ks = 0; ks < 16; ks += 8) {
            u32 a0 = As[cur][(wm * 16 + g)     * AS_STRIDE + ks + cc];
            u32 a1 = As[cur][(wm * 16 + g + 8) * AS_STRIDE + ks + cc];
            u32 a2 = As[cur][(wm * 16 + g)     * AS_STRIDE + ks + cc + 4];
            u32 a3 = As[cur][(wm * 16 + g + 8) * AS_STRIDE + ks + cc + 4];
            const u32* b0p = &Bs[cur][(ks + cc)     * BS_STRIDE + wn * 64 + g];
            const u32* b1p = &Bs[cur][(ks + cc + 4) * BS_STRIDE + wn * 64 + g];
#pragma unroll
            for (int j = 0; j < 8; j++) {
                u32 b0 = b0p[j * 8];
                u32 b1 = b1p[j * 8];
                MMA_TF32(C[j][0], C[j][1], C[j][2], C[j][3], a0, a1, a2, a3, b0, b1);
            }
        }
        if (more) {
            int nxt = cur ^ 1;
            As[nxt][asw + 0] = f2tf32(av.x); As[nxt][asw + 1] = f2tf32(av.y);
            As[nxt][asw + 2] = f2tf32(av.z); As[nxt][asw + 3] = f2tf32(av.w);
#pragma unroll
            for (int l = 0; l < 2; l++) {
                Bs[nxt][bsw + l * 4 + 0] = f2tf32(bv[l].x);
                Bs[nxt][bsw + l * 4 + 1] = f2tf32(bv[l].y);
                Bs[nxt][bsw + l * 4 + 2] = f2tf32(bv[l].z);
                Bs[nxt][bsw + l * 4 + 3] = f2tf32(bv[l].w);
            }
            __syncthreads();
        }
    }

    int idx0 = wm * 16 + g, idx1 = idx0 + 8;
    bool ok0 = idx0 < nrows, ok1 = idx1 < nrows;
    int r0 = rows[idx0], r1 = rows[idx1];
    float w00 = g_w0[r0], w01 = g_w1[r0];
    float w10 = g_w0[r1], w11 = g_w1[r1];
#pragma unroll
    for (int j = 0; j < 8; j++) {
        int lc = wn * 64 + j * 8 + 2 * cc;
        int col = bc * 128 + lc;
        float bx = sB[lc],     e0x = sE0[lc],     e1x = sE1[lc];
        float by = sB[lc + 1], e0y = sE0[lc + 1], e1y = sE1[lc + 1];
        if (ok0) {
            float2 st;
            st.x = fmaxf(C[j][0] + bx + w00 * e0x + w01 * e1x, 0.f);
            st.y = fmaxf(C[j][1] + by + w00 * e0y + w01 * e1y, 0.f);
            *(float2*)&g_add[((size_t)r0 << 8) + col] = st;
        }
        if (ok1) {
            float2 st;
            st.x = fmaxf(C[j][2] + bx + w10 * e0x + w11 * e1x, 0.f);
            st.y = fmaxf(C[j][3] + by + w10 * e0y + w11 * e1y, 0.f);
            *(float2*)&g_add[((size_t)r1 << 8) + col] = st;
        }
    }
}

// ============================================================================
// L5: copyE (0..319, FIRST — chunks never touched by scatter adds)
//     + scatter (320..4415)   [PDL secondary]
// ============================================================================
__global__ __launch_bounds__(256) void scatterKernel(
    float* __restrict__ out, const float* __restrict__ emb)
{
    cudaTriggerProgrammaticLaunchCompletion();
    int blk = blockIdx.x, tid = threadIdx.x;
    if (blk < CPY_E) {   // disjoint from scatter-add region; overlaps gemm1
        copyChunk((float4*)out, (const float4*)emb, mapE(blk), tid);
        return;
    }
    cudaGridDependencySynchronize();
    int sblk = blk - CPY_E;
    int b = sblk >> 7;
    int c = sblk & 127;
    int h = tid;
    if (!g_bhas[b]) return;
    int cnt = g_ccnt[b * 128 + c];
    if (cnt == 0) return;
    const int* list = g_clist + ((size_t)(b * 128 + c) << 9);
    float s = 0.f;
    for (int i = 0; i < cnt; i++) {
        int r = b * Nc + list[i];
        size_t o = ((size_t)r << 8) + h;
        s += g_hn[r] ? g_add[o] : g_node[o];
    }
    out[((size_t)b * Lc + c) * Hc + h] += s;
}

// ---------------- launch -----------------------------------------------------
extern "C" void kernel_launch(void* const* d_in, const int* in_sizes, int n_in,
                              void* d_out, int out_size)
{
    const float* emb     = (const float*)d_in[0];
    const float* W_trip  = (const float*)d_in[1];
    const float* b_trip  = (const float*)d_in[2];
    const float* edge_e  = (const float*)d_in[3];
    const float* W_attn  = (const float*)d_in[4];
    const float* b_attn  = (const float*)d_in[5];
    const float* W_gat   = (const float*)d_in[6];
    const float* b_gat   = (const float*)d_in[7];
    const int*   asp_st  = (const int*)d_in[8];
    const int*   asp_len = (const int*)d_in[9];
    const int*   opi_st  = (const int*)d_in[10];
    const int*   opi_len = (const int*)d_in[11];
    const int*   sent_id = (const int*)d_in[12];
    float* out = (float*)d_out;

    mega0Kernel<<<304 + CPY_A, 256>>>(out, emb, W_trip, asp_st, asp_len,
                                      opi_st, opi_len, edge_e, W_attn, W_gat);

    cudaLaunchAttribute attr[1];
    attr[0].id = cudaLaunchAttributeProgrammaticStreamSerialization;
    attr[0].val.programmaticStreamSerializationAllowed = 1;

    {
        cudaLaunchConfig_t cfg = {};
        cfg.gridDim = dim3(4096 + CPY_B);
        cfg.blockDim = dim3(256);
        cfg.stream = 0;
        cfg.attrs = attr;
        cfg.numAttrs = 1;
        cudaLaunchKernelEx(&cfg, nodeStatsKernel, out, emb, asp_st, asp_len,
                           opi_st, opi_len, sent_id, W_trip, b_trip, W_attn);
    }
    {
        cudaLaunchConfig_t cfg = {};
        cfg.gridDim = dim3(2048 + CPY_C);
        cfg.blockDim = dim3(256);
        cfg.stream = 0;
        cfg.attrs = attr;
        cfg.numAttrs = 1;
        cudaLaunchKernelEx(&cfg, edgeKernel, out, emb, b_attn);
    }
    {
        cudaLaunchConfig_t cfg = {};
        cfg.gridDim = dim3(512 + CPY_D);
        cfg.blockDim = dim3(256);
        cfg.stream = 0;
        cfg.attrs = attr;
        cfg.numAttrs = 1;
        cudaLaunchKernelEx(&cfg, gemm1Kernel, out, emb, W_gat, b_gat);
    }
    {
        cudaLaunchConfig_t cfg = {};
        cfg.gridDim = dim3(Bc * 128 + CPY_E);
        cfg.blockDim = dim3(256);
        cfg.stream = 0;
        cfg.attrs = attr;
        cfg.numAttrs = 1;
        cudaLaunchKernelEx(&cfg, scatterKernel, out, emb);
    }
}